// round 1
// baseline (speedup 1.0000x reference)
#include <cuda_runtime.h>
#include <cuda_bf16.h>
#include <math.h>

// Problem constants (match reference shapes)
#define H        256
#define SEQ_LEN  10
#define MAX_ENT  20000
#define MAX_B    2048
#define MAX_N    327680

// Scratch (device globals — no allocation allowed)
__device__ float g_entW1[(size_t)MAX_ENT * H];   // ent_embeds @ W1
__device__ float g_qterm[(size_t)MAX_B * H];     // s@W2 + r@W3 + b
__device__ float g_scores[MAX_N];

// ---------------------------------------------------------------------------
// Kernel 1: entW1[M,256] = ent_embeds[M,256] @ W_attn[0:256, 0:256]
// Classic 128x128 tile, 8x8 microtile, BK=8, 256 threads.
// ---------------------------------------------------------------------------
__global__ __launch_bounds__(256) void sgemm_entW1(
    const float* __restrict__ A, const float* __restrict__ W, int M)
{
    const int BM = 128, BN = 128, BK = 8;
    __shared__ float As[BK][BM];
    __shared__ float Bs[BK][BN];

    int tid  = threadIdx.x;
    int row0 = blockIdx.y * BM;
    int col0 = blockIdx.x * BN;

    int ar = tid >> 1;            // 0..127
    int ac = (tid & 1) * 4;       // 0 or 4
    int bk = tid >> 5;            // 0..7
    int bj = (tid & 31) * 4;      // 0..124
    int tx = tid & 15;
    int ty = tid >> 4;

    float acc[8][8];
#pragma unroll
    for (int i = 0; i < 8; i++)
#pragma unroll
        for (int j = 0; j < 8; j++) acc[i][j] = 0.f;

    for (int k0 = 0; k0 < H; k0 += BK) {
        float4 av = make_float4(0.f, 0.f, 0.f, 0.f);
        if (row0 + ar < M)
            av = *reinterpret_cast<const float4*>(A + (size_t)(row0 + ar) * H + k0 + ac);
        float4 bv = *reinterpret_cast<const float4*>(W + (size_t)(k0 + bk) * H + col0 + bj);

        As[ac + 0][ar] = av.x;
        As[ac + 1][ar] = av.y;
        As[ac + 2][ar] = av.z;
        As[ac + 3][ar] = av.w;
        *reinterpret_cast<float4*>(&Bs[bk][bj]) = bv;
        __syncthreads();

#pragma unroll
        for (int kk = 0; kk < BK; kk++) {
            float a[8], b[8];
            *reinterpret_cast<float4*>(a)     = *reinterpret_cast<float4*>(&As[kk][ty * 4]);
            *reinterpret_cast<float4*>(a + 4) = *reinterpret_cast<float4*>(&As[kk][64 + ty * 4]);
            *reinterpret_cast<float4*>(b)     = *reinterpret_cast<float4*>(&Bs[kk][tx * 4]);
            *reinterpret_cast<float4*>(b + 4) = *reinterpret_cast<float4*>(&Bs[kk][64 + tx * 4]);
#pragma unroll
            for (int i = 0; i < 8; i++)
#pragma unroll
                for (int j = 0; j < 8; j++)
                    acc[i][j] = fmaf(a[i], b[j], acc[i][j]);
        }
        __syncthreads();
    }

#pragma unroll
    for (int i = 0; i < 8; i++) {
        int rr = row0 + ((i < 4) ? (ty * 4 + i) : (64 + ty * 4 + (i - 4)));
        if (rr >= M) continue;
        float4 v0 = make_float4(acc[i][0], acc[i][1], acc[i][2], acc[i][3]);
        float4 v1 = make_float4(acc[i][4], acc[i][5], acc[i][6], acc[i][7]);
        *reinterpret_cast<float4*>(g_entW1 + (size_t)rr * H + col0 + tx * 4)      = v0;
        *reinterpret_cast<float4*>(g_entW1 + (size_t)rr * H + col0 + 64 + tx * 4) = v1;
    }
}

// ---------------------------------------------------------------------------
// Kernel 2: qterm[q, j] = b[j] + sum_k s_emb[q,k]*W2[k,j] + r_emb[q,k]*W3[k,j]
// 16 queries per block, thread j = column.
// ---------------------------------------------------------------------------
__global__ __launch_bounds__(256) void qterm_kernel(
    const int* __restrict__ s, const int* __restrict__ r,
    const float* __restrict__ ent, const float* __restrict__ rel,
    const float* __restrict__ W, const float* __restrict__ b, int B)
{
    const int QB = 16;
    __shared__ float s_sh[QB][H];
    __shared__ float r_sh[QB][H];
    __shared__ int sidx[QB], ridx[QB];

    int q0  = blockIdx.x * QB;
    int tid = threadIdx.x;

    if (tid < QB) {
        int q = q0 + tid;
        sidx[tid] = (q < B) ? s[q] : 0;
        ridx[tid] = (q < B) ? r[q] : 0;
    }
    __syncthreads();

    for (int idx = tid; idx < QB * H; idx += 256) {
        int qq = idx >> 8, k = idx & (H - 1);
        s_sh[qq][k] = ent[(size_t)sidx[qq] * H + k];
        r_sh[qq][k] = rel[(size_t)ridx[qq] * H + k];
    }
    __syncthreads();

    int j = tid;
    float bj = b[j];
    float acc[QB];
#pragma unroll
    for (int qq = 0; qq < QB; qq++) acc[qq] = bj;

    for (int k = 0; k < H; k++) {
        float w2 = W[(size_t)(H + k) * H + j];
        float w3 = W[(size_t)(2 * H + k) * H + j];
#pragma unroll
        for (int qq = 0; qq < QB; qq++)
            acc[qq] = fmaf(s_sh[qq][k], w2, fmaf(r_sh[qq][k], w3, acc[qq]));
    }

#pragma unroll
    for (int qq = 0; qq < QB; qq++) {
        int q = q0 + qq;
        if (q < B) g_qterm[(size_t)q * H + j] = acc[qq];
    }
}

// ---------------------------------------------------------------------------
// Kernel 3: per-neighbor score. One warp per neighbor.
// score[n] = sum_j v_s[j] * tanh(entW1[nbr_ids[n], j] + qterm[q, j])
// ---------------------------------------------------------------------------
__global__ __launch_bounds__(256) void score_kernel(
    const int* __restrict__ seg_ids, const int* __restrict__ nbr_ids,
    const float* __restrict__ v_s, int N)
{
    int gw   = (int)((blockIdx.x * (unsigned)blockDim.x + threadIdx.x) >> 5);
    int lane = threadIdx.x & 31;
    if (gw >= N) return;

    int q   = seg_ids[gw] / SEQ_LEN;
    int nid = nbr_ids[gw];

    const float4* e  = reinterpret_cast<const float4*>(g_entW1 + (size_t)nid * H) + lane * 2;
    const float4* qt = reinterpret_cast<const float4*>(g_qterm + (size_t)q * H) + lane * 2;
    const float4* vv = reinterpret_cast<const float4*>(v_s) + lane * 2;

    float4 a0 = e[0],  a1 = e[1];
    float4 b0 = qt[0], b1 = qt[1];
    float4 v0 = vv[0], v1 = vv[1];

    float p = tanhf(a0.x + b0.x) * v0.x;
    p = fmaf(tanhf(a0.y + b0.y), v0.y, p);
    p = fmaf(tanhf(a0.z + b0.z), v0.z, p);
    p = fmaf(tanhf(a0.w + b0.w), v0.w, p);
    p = fmaf(tanhf(a1.x + b1.x), v1.x, p);
    p = fmaf(tanhf(a1.y + b1.y), v1.y, p);
    p = fmaf(tanhf(a1.z + b1.z), v1.z, p);
    p = fmaf(tanhf(a1.w + b1.w), v1.w, p);

#pragma unroll
    for (int off = 16; off > 0; off >>= 1)
        p += __shfl_xor_sync(0xFFFFFFFFu, p, off);

    if (lane == 0) g_scores[gw] = p;
}

// ---------------------------------------------------------------------------
// Kernel 4: fused segment softmax + weighted aggregation + output assembly.
// One warp per segment. seg_ids is sorted -> binary search for range.
// out row layout: [agg(256) | ss(256) | rr(256)], zero row if segment empty.
// ---------------------------------------------------------------------------
__device__ __forceinline__ int lower_bound_i(const int* __restrict__ a, int n, int key)
{
    int lo = 0, hi = n;
    while (lo < hi) {
        int mid = (lo + hi) >> 1;
        if (a[mid] < key) lo = mid + 1; else hi = mid;
    }
    return lo;
}

__global__ __launch_bounds__(256) void agg_kernel(
    const int* __restrict__ s, const int* __restrict__ r,
    const int* __restrict__ nbr_ids, const int* __restrict__ seg_ids,
    const float* __restrict__ ent, const float* __restrict__ rel,
    float* __restrict__ out, int N, int num_seg)
{
    int seg  = (int)((blockIdx.x * (unsigned)blockDim.x + threadIdx.x) >> 5);
    int lane = threadIdx.x & 31;
    if (seg >= num_seg) return;

    float* orow = out + (size_t)seg * (3 * H);

    int lo = lower_bound_i(seg_ids, N, seg);
    int hi = lower_bound_i(seg_ids, N, seg + 1);

    if (lo >= hi) {
        // Empty segment: whole row is zero (mask semantics).
        float4 z = make_float4(0.f, 0.f, 0.f, 0.f);
        float4* w = reinterpret_cast<float4*>(orow) + lane * 2;
#pragma unroll
        for (int c = 0; c < 3; c++) {
            w[c * 64 + 0] = z;
            w[c * 64 + 1] = z;
        }
        return;
    }

    // Pass 1: segment max
    float m = -INFINITY;
    for (int i = lo + lane; i < hi; i += 32)
        m = fmaxf(m, g_scores[i]);
#pragma unroll
    for (int off = 16; off > 0; off >>= 1)
        m = fmaxf(m, __shfl_xor_sync(0xFFFFFFFFu, m, off));

    // Pass 2: denominator
    float dsum = 0.f;
    for (int i = lo + lane; i < hi; i += 32)
        dsum += expf(g_scores[i] - m);
#pragma unroll
    for (int off = 16; off > 0; off >>= 1)
        dsum += __shfl_xor_sync(0xFFFFFFFFu, dsum, off);
    float inv = 1.f / dsum;

    // Pass 3: weighted sum of neighbor embeddings (warp-cooperative over H)
    float4 acc0 = make_float4(0.f, 0.f, 0.f, 0.f);
    float4 acc1 = make_float4(0.f, 0.f, 0.f, 0.f);
    for (int i = lo; i < hi; i++) {
        float w  = expf(g_scores[i] - m) * inv;   // uniform across warp (broadcast load)
        int nid  = nbr_ids[i];                     // broadcast load
        const float4* em = reinterpret_cast<const float4*>(ent + (size_t)nid * H) + lane * 2;
        float4 e0 = em[0], e1 = em[1];
        acc0.x = fmaf(w, e0.x, acc0.x); acc0.y = fmaf(w, e0.y, acc0.y);
        acc0.z = fmaf(w, e0.z, acc0.z); acc0.w = fmaf(w, e0.w, acc0.w);
        acc1.x = fmaf(w, e1.x, acc1.x); acc1.y = fmaf(w, e1.y, acc1.y);
        acc1.z = fmaf(w, e1.z, acc1.z); acc1.w = fmaf(w, e1.w, acc1.w);
    }

    int q   = seg / SEQ_LEN;
    int sid = s[q];
    int rid = r[q];

    float4* w4 = reinterpret_cast<float4*>(orow) + lane * 2;
    w4[0] = acc0;
    w4[1] = acc1;

    const float4* se = reinterpret_cast<const float4*>(ent + (size_t)sid * H) + lane * 2;
    w4[64 + 0] = se[0];
    w4[64 + 1] = se[1];

    const float4* re = reinterpret_cast<const float4*>(rel + (size_t)rid * H) + lane * 2;
    w4[128 + 0] = re[0];
    w4[128 + 1] = re[1];
}

// ---------------------------------------------------------------------------
extern "C" void kernel_launch(void* const* d_in, const int* in_sizes, int n_in,
                              void* d_out, int out_size)
{
    const int*   s    = (const int*)d_in[0];
    const int*   r    = (const int*)d_in[1];
    const int*   nbr  = (const int*)d_in[2];
    const int*   seg  = (const int*)d_in[3];
    const float* ent  = (const float*)d_in[4];
    const float* rel  = (const float*)d_in[5];
    const float* W    = (const float*)d_in[6];
    const float* b    = (const float*)d_in[7];
    const float* vs   = (const float*)d_in[8];
    float*       out  = (float*)d_out;

    int B  = in_sizes[0];
    int N  = in_sizes[2];
    int NE = in_sizes[4] / H;
    int num_seg = B * SEQ_LEN;

    // K1: entW1 = ent_embeds @ W1
    dim3 g1(2, (NE + 127) / 128);
    sgemm_entW1<<<g1, 256>>>(ent, W, NE);

    // K2: qterm = s_emb@W2 + r_emb@W3 + b
    qterm_kernel<<<(B + 15) / 16, 256>>>(s, r, ent, rel, W, b, B);

    // K3: per-neighbor scores (1 warp / neighbor)
    int blocks3 = (N + 7) / 8;   // 8 warps per 256-thread block
    score_kernel<<<blocks3, 256>>>(seg, nbr, vs, N);

    // K4: segment softmax + aggregation + output assembly (1 warp / segment)
    int blocks4 = (num_seg + 7) / 8;
    agg_kernel<<<blocks4, 256>>>(s, r, nbr, seg, ent, rel, out, N, num_seg);
}

// round 5
// speedup vs baseline: 1.0612x; 1.0612x over previous
#include <cuda_runtime.h>
#include <cuda_bf16.h>
#include <math.h>

// Problem constants (match reference shapes)
#define H        256
#define SEQ_LEN  10
#define MAX_ENT  20000
#define MAX_B    2048
#define MAX_N    327680
#define MAX_SEG  (MAX_B * SEQ_LEN)

// Scratch (device globals — no allocation allowed)
__device__ float g_entW1[(size_t)MAX_ENT * H];   // ent_embeds @ W1
__device__ float g_qterm[(size_t)MAX_B * H];     // s@W2 + r@W3 + b
__device__ float g_scores[MAX_N];
__device__ int   g_off[MAX_SEG + 1];             // segment offsets

__device__ __forceinline__ float tanh_approx(float x)
{
    float y;
    asm("tanh.approx.f32 %0, %1;" : "=f"(y) : "f"(x));
    return y;
}

// Packed f32x2 helpers (sm_103a: FFMA2 only reachable via PTX fma.rn.f32x2)
__device__ __forceinline__ unsigned long long dup_f32x2(float x)
{
    unsigned long long u;
    asm("mov.b64 %0, {%1, %1};" : "=l"(u) : "f"(x));
    return u;
}
__device__ __forceinline__ void ffma2(unsigned long long& d,
                                      unsigned long long a,
                                      unsigned long long b)
{
    asm("fma.rn.f32x2 %0, %1, %2, %0;" : "+l"(d) : "l"(a), "l"(b));
}
__device__ __forceinline__ float2 unpack_f32x2(unsigned long long u)
{
    float2 f;
    asm("mov.b64 {%0, %1}, %2;" : "=f"(f.x), "=f"(f.y) : "l"(u));
    return f;
}

// ---------------------------------------------------------------------------
// Kernel 1: entW1[M,256] = ent_embeds[M,256] @ W_attn[0:256, 0:256]
// 128x128 tile, 8x8 microtile (as 8x4 f32x2 pairs), BK=8, 256 threads,
// register prefetch + packed FFMA2 mainloop.
// ---------------------------------------------------------------------------
__global__ __launch_bounds__(256) void sgemm_entW1(
    const float* __restrict__ A, const float* __restrict__ W, int M)
{
    const int BM = 128, BK = 8;
    __shared__ float As[BK][BM];
    __shared__ float Bs[BK][BM];

    int tid  = threadIdx.x;
    int row0 = blockIdx.y * BM;
    int col0 = blockIdx.x * BM;

    int ar = tid >> 1;            // 0..127
    int ac = (tid & 1) * 4;       // 0 or 4
    int bk = tid >> 5;            // 0..7
    int bj = (tid & 31) * 4;      // 0..124
    int tx = tid & 15;
    int ty = tid >> 4;

    // acc2[i][jp]: row i (8 rows), column pair jp (4 pairs = 8 cols)
    unsigned long long acc2[8][4];
#pragma unroll
    for (int i = 0; i < 8; i++)
#pragma unroll
        for (int j = 0; j < 4; j++) acc2[i][j] = 0ull;

    // prologue: stage k0 = 0
    float4 av = make_float4(0.f, 0.f, 0.f, 0.f);
    if (row0 + ar < M)
        av = *reinterpret_cast<const float4*>(A + (size_t)(row0 + ar) * H + ac);
    float4 bv = *reinterpret_cast<const float4*>(W + (size_t)bk * H + col0 + bj);

    for (int k0 = 0; k0 < H; k0 += BK) {
        As[ac + 0][ar] = av.x;
        As[ac + 1][ar] = av.y;
        As[ac + 2][ar] = av.z;
        As[ac + 3][ar] = av.w;
        *reinterpret_cast<float4*>(&Bs[bk][bj]) = bv;
        __syncthreads();

        // prefetch next tile while computing this one
        if (k0 + BK < H) {
            if (row0 + ar < M)
                av = *reinterpret_cast<const float4*>(A + (size_t)(row0 + ar) * H + k0 + BK + ac);
            bv = *reinterpret_cast<const float4*>(W + (size_t)(k0 + BK + bk) * H + col0 + bj);
        }

#pragma unroll
        for (int kk = 0; kk < BK; kk++) {
            float a[8];
            *reinterpret_cast<float4*>(a)     = *reinterpret_cast<float4*>(&As[kk][ty * 4]);
            *reinterpret_cast<float4*>(a + 4) = *reinterpret_cast<float4*>(&As[kk][64 + ty * 4]);

            ulonglong2 b01 = *reinterpret_cast<ulonglong2*>(&Bs[kk][tx * 4]);
            ulonglong2 b23 = *reinterpret_cast<ulonglong2*>(&Bs[kk][64 + tx * 4]);

            unsigned long long ap[8];
#pragma unroll
            for (int i = 0; i < 8; i++) ap[i] = dup_f32x2(a[i]);

#pragma unroll
            for (int i = 0; i < 8; i++) {
                ffma2(acc2[i][0], ap[i], b01.x);
                ffma2(acc2[i][1], ap[i], b01.y);
                ffma2(acc2[i][2], ap[i], b23.x);
                ffma2(acc2[i][3], ap[i], b23.y);
            }
        }
        __syncthreads();
    }

#pragma unroll
    for (int i = 0; i < 8; i++) {
        int rr = row0 + ((i < 4) ? (ty * 4 + i) : (64 + ty * 4 + (i - 4)));
        if (rr >= M) continue;
        float2 p0 = unpack_f32x2(acc2[i][0]);
        float2 p1 = unpack_f32x2(acc2[i][1]);
        float2 p2 = unpack_f32x2(acc2[i][2]);
        float2 p3 = unpack_f32x2(acc2[i][3]);
        float4 v0 = make_float4(p0.x, p0.y, p1.x, p1.y);
        float4 v1 = make_float4(p2.x, p2.y, p3.x, p3.y);
        *reinterpret_cast<float4*>(g_entW1 + (size_t)rr * H + col0 + tx * 4)      = v0;
        *reinterpret_cast<float4*>(g_entW1 + (size_t)rr * H + col0 + 64 + tx * 4) = v1;
    }
}

// ---------------------------------------------------------------------------
// Kernel 2: qterm[q, j] = b[j] + sum_k s_emb[q,k]*W2[k,j] + r_emb[q,k]*W3[k,j]
// ---------------------------------------------------------------------------
__global__ __launch_bounds__(256) void qterm_kernel(
    const int* __restrict__ s, const int* __restrict__ r,
    const float* __restrict__ ent, const float* __restrict__ rel,
    const float* __restrict__ W, const float* __restrict__ b, int B)
{
    const int QB = 16;
    __shared__ float s_sh[QB][H];
    __shared__ float r_sh[QB][H];
    __shared__ int sidx[QB], ridx[QB];

    int q0  = blockIdx.x * QB;
    int tid = threadIdx.x;

    if (tid < QB) {
        int q = q0 + tid;
        sidx[tid] = (q < B) ? s[q] : 0;
        ridx[tid] = (q < B) ? r[q] : 0;
    }
    __syncthreads();

    for (int idx = tid; idx < QB * H; idx += 256) {
        int qq = idx >> 8, k = idx & (H - 1);
        s_sh[qq][k] = ent[(size_t)sidx[qq] * H + k];
        r_sh[qq][k] = rel[(size_t)ridx[qq] * H + k];
    }
    __syncthreads();

    int j = tid;
    float bj = b[j];
    float acc[QB];
#pragma unroll
    for (int qq = 0; qq < QB; qq++) acc[qq] = bj;

    for (int k = 0; k < H; k++) {
        float w2 = W[(size_t)(H + k) * H + j];
        float w3 = W[(size_t)(2 * H + k) * H + j];
#pragma unroll
        for (int qq = 0; qq < QB; qq++)
            acc[qq] = fmaf(s_sh[qq][k], w2, fmaf(r_sh[qq][k], w3, acc[qq]));
    }

#pragma unroll
    for (int qq = 0; qq < QB; qq++) {
        int q = q0 + qq;
        if (q < B) g_qterm[(size_t)q * H + j] = acc[qq];
    }
}

// ---------------------------------------------------------------------------
// Kernel 2b: segment offsets from sorted seg_ids.
// g_off[t] = first index i with seg_ids[i] >= t, for t in [0, num_seg].
// ---------------------------------------------------------------------------
__global__ __launch_bounds__(256) void boundary_kernel(
    const int* __restrict__ seg_ids, int N, int num_seg)
{
    int i = blockIdx.x * blockDim.x + threadIdx.x;
    if (i >= N) return;
    int sc = seg_ids[i];
    int sp = (i == 0) ? -1 : seg_ids[i - 1];
    for (int t = sp + 1; t <= sc; t++) g_off[t] = i;
    if (i == N - 1) {
        for (int t = sc + 1; t <= num_seg; t++) g_off[t] = N;
    }
}

// ---------------------------------------------------------------------------
// Kernel 3: per-neighbor score. One warp per neighbor.
// score[n] = sum_j v_s[j] * tanh(entW1[nbr_ids[n], j] + qterm[q, j])
// ---------------------------------------------------------------------------
__global__ __launch_bounds__(256) void score_kernel(
    const int* __restrict__ seg_ids, const int* __restrict__ nbr_ids,
    const float* __restrict__ v_s, int N)
{
    int gw   = (int)((blockIdx.x * (unsigned)blockDim.x + threadIdx.x) >> 5);
    int lane = threadIdx.x & 31;
    if (gw >= N) return;

    int q   = seg_ids[gw] / SEQ_LEN;
    int nid = nbr_ids[gw];

    const float4* e  = reinterpret_cast<const float4*>(g_entW1 + (size_t)nid * H) + lane * 2;
    const float4* qt = reinterpret_cast<const float4*>(g_qterm + (size_t)q * H) + lane * 2;
    const float4* vv = reinterpret_cast<const float4*>(v_s) + lane * 2;

    float4 a0 = e[0],  a1 = e[1];
    float4 b0 = qt[0], b1 = qt[1];
    float4 v0 = vv[0], v1 = vv[1];

    float p = tanh_approx(a0.x + b0.x) * v0.x;
    p = fmaf(tanh_approx(a0.y + b0.y), v0.y, p);
    p = fmaf(tanh_approx(a0.z + b0.z), v0.z, p);
    p = fmaf(tanh_approx(a0.w + b0.w), v0.w, p);
    p = fmaf(tanh_approx(a1.x + b1.x), v1.x, p);
    p = fmaf(tanh_approx(a1.y + b1.y), v1.y, p);
    p = fmaf(tanh_approx(a1.z + b1.z), v1.z, p);
    p = fmaf(tanh_approx(a1.w + b1.w), v1.w, p);

#pragma unroll
    for (int off = 16; off > 0; off >>= 1)
        p += __shfl_xor_sync(0xFFFFFFFFu, p, off);

    if (lane == 0) g_scores[gw] = p;
}

// ---------------------------------------------------------------------------
// Kernel 4: fused segment softmax + weighted aggregation + output assembly.
// One warp per segment, offsets precomputed (no binary search).
// out row layout: [agg(256) | ss(256) | rr(256)], zero row if segment empty.
// ---------------------------------------------------------------------------
__global__ __launch_bounds__(256) void agg_kernel(
    const int* __restrict__ s, const int* __restrict__ r,
    const int* __restrict__ nbr_ids,
    const float* __restrict__ ent, const float* __restrict__ rel,
    float* __restrict__ out, int num_seg)
{
    int seg  = (int)((blockIdx.x * (unsigned)blockDim.x + threadIdx.x) >> 5);
    int lane = threadIdx.x & 31;
    if (seg >= num_seg) return;

    float* orow = out + (size_t)seg * (3 * H);

    int lo = g_off[seg];
    int hi = g_off[seg + 1];

    if (lo >= hi) {
        // Empty segment: whole row is zero (mask semantics).
        float4 z = make_float4(0.f, 0.f, 0.f, 0.f);
        float4* w = reinterpret_cast<float4*>(orow) + lane * 2;
#pragma unroll
        for (int c = 0; c < 3; c++) {
            w[c * 64 + 0] = z;
            w[c * 64 + 1] = z;
        }
        return;
    }

    // Pass 1: segment max
    float m = -INFINITY;
    for (int i = lo + lane; i < hi; i += 32)
        m = fmaxf(m, g_scores[i]);
#pragma unroll
    for (int off = 16; off > 0; off >>= 1)
        m = fmaxf(m, __shfl_xor_sync(0xFFFFFFFFu, m, off));

    // Pass 2: denominator
    float dsum = 0.f;
    for (int i = lo + lane; i < hi; i += 32)
        dsum += __expf(g_scores[i] - m);
#pragma unroll
    for (int off = 16; off > 0; off >>= 1)
        dsum += __shfl_xor_sync(0xFFFFFFFFu, dsum, off);
    float inv = 1.f / dsum;

    // Pass 3: weighted sum of neighbor embeddings (warp-cooperative over H)
    float4 acc0 = make_float4(0.f, 0.f, 0.f, 0.f);
    float4 acc1 = make_float4(0.f, 0.f, 0.f, 0.f);
    for (int i = lo; i < hi; i++) {
        float w  = __expf(g_scores[i] - m) * inv;  // uniform across warp
        int nid  = nbr_ids[i];                      // broadcast load
        const float4* em = reinterpret_cast<const float4*>(ent + (size_t)nid * H) + lane * 2;
        float4 e0 = em[0], e1 = em[1];
        acc0.x = fmaf(w, e0.x, acc0.x); acc0.y = fmaf(w, e0.y, acc0.y);
        acc0.z = fmaf(w, e0.z, acc0.z); acc0.w = fmaf(w, e0.w, acc0.w);
        acc1.x = fmaf(w, e1.x, acc1.x); acc1.y = fmaf(w, e1.y, acc1.y);
        acc1.z = fmaf(w, e1.z, acc1.z); acc1.w = fmaf(w, e1.w, acc1.w);
    }

    int q   = seg / SEQ_LEN;
    int sid = s[q];
    int rid = r[q];

    float4* w4 = reinterpret_cast<float4*>(orow) + lane * 2;
    w4[0] = acc0;
    w4[1] = acc1;

    const float4* se = reinterpret_cast<const float4*>(ent + (size_t)sid * H) + lane * 2;
    w4[64 + 0] = se[0];
    w4[64 + 1] = se[1];

    const float4* re = reinterpret_cast<const float4*>(rel + (size_t)rid * H) + lane * 2;
    w4[128 + 0] = re[0];
    w4[128 + 1] = re[1];
}

// ---------------------------------------------------------------------------
extern "C" void kernel_launch(void* const* d_in, const int* in_sizes, int n_in,
                              void* d_out, int out_size)
{
    const int*   s    = (const int*)d_in[0];
    const int*   r    = (const int*)d_in[1];
    const int*   nbr  = (const int*)d_in[2];
    const int*   seg  = (const int*)d_in[3];
    const float* ent  = (const float*)d_in[4];
    const float* rel  = (const float*)d_in[5];
    const float* W    = (const float*)d_in[6];
    const float* b    = (const float*)d_in[7];
    const float* vs   = (const float*)d_in[8];
    float*       out  = (float*)d_out;

    int B  = in_sizes[0];
    int N  = in_sizes[2];
    int NE = in_sizes[4] / H;
    int num_seg = B * SEQ_LEN;

    // K1: entW1 = ent_embeds @ W1
    dim3 g1(2, (NE + 127) / 128);
    sgemm_entW1<<<g1, 256>>>(ent, W, NE);

    // K2: qterm = s_emb@W2 + r_emb@W3 + b
    qterm_kernel<<<(B + 15) / 16, 256>>>(s, r, ent, rel, W, b, B);

    // K2b: segment offsets (sorted seg_ids)
    boundary_kernel<<<(N + 255) / 256, 256>>>(seg, N, num_seg);

    // K3: per-neighbor scores (1 warp / neighbor)
    int blocks3 = (N + 7) / 8;
    score_kernel<<<blocks3, 256>>>(seg, nbr, vs, N);

    // K4: segment softmax + aggregation + output assembly (1 warp / segment)
    int blocks4 = (num_seg + 7) / 8;
    agg_kernel<<<blocks4, 256>>>(s, r, nbr, ent, rel, out, num_seg);
}

// round 9
// speedup vs baseline: 1.2253x; 1.1546x over previous
#include <cuda_runtime.h>
#include <cuda_bf16.h>
#include <math.h>

// Problem constants (match reference shapes)
#define H        256
#define SEQ_LEN  10
#define MAX_ENT  20000
#define MAX_B    2048
#define MAX_N    327680
#define MAX_SEG  (MAX_B * SEQ_LEN)

// Scratch (device globals — no allocation allowed)
__device__ float g_entW1[(size_t)MAX_ENT * H];   // ent_embeds @ W1
__device__ float g_qterm[(size_t)MAX_B * H];     // s@W2 + r@W3 + b
__device__ int   g_off[MAX_SEG + 1];             // segment offsets

__device__ __forceinline__ float tanh_approx(float x)
{
    float y;
    asm("tanh.approx.f32 %0, %1;" : "=f"(y) : "f"(x));
    return y;
}

// Packed f32x2 helpers (sm_103a: FFMA2 only reachable via PTX fma.rn.f32x2)
__device__ __forceinline__ unsigned long long dup_f32x2(float x)
{
    unsigned long long u;
    asm("mov.b64 %0, {%1, %1};" : "=l"(u) : "f"(x));
    return u;
}
__device__ __forceinline__ void ffma2(unsigned long long& d,
                                      unsigned long long a,
                                      unsigned long long b)
{
    asm("fma.rn.f32x2 %0, %1, %2, %0;" : "+l"(d) : "l"(a), "l"(b));
}
__device__ __forceinline__ float2 unpack_f32x2(unsigned long long u)
{
    float2 f;
    asm("mov.b64 {%0, %1}, %2;" : "=f"(f.x), "=f"(f.y) : "l"(u));
    return f;
}

// ---------------------------------------------------------------------------
// Kernel 1: entW1[M,256] = ent_embeds[M,256] @ W_attn[0:256, 0:256]
// 128x128 tile, 8x8 microtile (as 8x4 f32x2 pairs), BK=8, 256 threads,
// register prefetch + packed FFMA2 mainloop.
// ---------------------------------------------------------------------------
__global__ __launch_bounds__(256) void sgemm_entW1(
    const float* __restrict__ A, const float* __restrict__ W, int M)
{
    const int BM = 128, BK = 8;
    __shared__ float As[BK][BM];
    __shared__ float Bs[BK][BM];

    int tid  = threadIdx.x;
    int row0 = blockIdx.y * BM;
    int col0 = blockIdx.x * BM;

    int ar = tid >> 1;            // 0..127
    int ac = (tid & 1) * 4;       // 0 or 4
    int bk = tid >> 5;            // 0..7
    int bj = (tid & 31) * 4;      // 0..124
    int tx = tid & 15;
    int ty = tid >> 4;

    unsigned long long acc2[8][4];
#pragma unroll
    for (int i = 0; i < 8; i++)
#pragma unroll
        for (int j = 0; j < 4; j++) acc2[i][j] = 0ull;

    float4 av = make_float4(0.f, 0.f, 0.f, 0.f);
    if (row0 + ar < M)
        av = *reinterpret_cast<const float4*>(A + (size_t)(row0 + ar) * H + ac);
    float4 bv = *reinterpret_cast<const float4*>(W + (size_t)bk * H + col0 + bj);

    for (int k0 = 0; k0 < H; k0 += BK) {
        As[ac + 0][ar] = av.x;
        As[ac + 1][ar] = av.y;
        As[ac + 2][ar] = av.z;
        As[ac + 3][ar] = av.w;
        *reinterpret_cast<float4*>(&Bs[bk][bj]) = bv;
        __syncthreads();

        if (k0 + BK < H) {
            if (row0 + ar < M)
                av = *reinterpret_cast<const float4*>(A + (size_t)(row0 + ar) * H + k0 + BK + ac);
            bv = *reinterpret_cast<const float4*>(W + (size_t)(k0 + BK + bk) * H + col0 + bj);
        }

#pragma unroll
        for (int kk = 0; kk < BK; kk++) {
            float a[8];
            *reinterpret_cast<float4*>(a)     = *reinterpret_cast<float4*>(&As[kk][ty * 4]);
            *reinterpret_cast<float4*>(a + 4) = *reinterpret_cast<float4*>(&As[kk][64 + ty * 4]);

            ulonglong2 b01 = *reinterpret_cast<ulonglong2*>(&Bs[kk][tx * 4]);
            ulonglong2 b23 = *reinterpret_cast<ulonglong2*>(&Bs[kk][64 + tx * 4]);

            unsigned long long ap[8];
#pragma unroll
            for (int i = 0; i < 8; i++) ap[i] = dup_f32x2(a[i]);

#pragma unroll
            for (int i = 0; i < 8; i++) {
                ffma2(acc2[i][0], ap[i], b01.x);
                ffma2(acc2[i][1], ap[i], b01.y);
                ffma2(acc2[i][2], ap[i], b23.x);
                ffma2(acc2[i][3], ap[i], b23.y);
            }
        }
        __syncthreads();
    }

#pragma unroll
    for (int i = 0; i < 8; i++) {
        int rr = row0 + ((i < 4) ? (ty * 4 + i) : (64 + ty * 4 + (i - 4)));
        if (rr >= M) continue;
        float2 p0 = unpack_f32x2(acc2[i][0]);
        float2 p1 = unpack_f32x2(acc2[i][1]);
        float2 p2 = unpack_f32x2(acc2[i][2]);
        float2 p3 = unpack_f32x2(acc2[i][3]);
        float4 v0 = make_float4(p0.x, p0.y, p1.x, p1.y);
        float4 v1 = make_float4(p2.x, p2.y, p3.x, p3.y);
        *reinterpret_cast<float4*>(g_entW1 + (size_t)rr * H + col0 + tx * 4)      = v0;
        *reinterpret_cast<float4*>(g_entW1 + (size_t)rr * H + col0 + 64 + tx * 4) = v1;
    }
}

// ---------------------------------------------------------------------------
// Kernel 2: qterm[q, j] = b[j] + sum_k s_emb[q,k]*W2[k,j] + r_emb[q,k]*W3[k,j]
// ---------------------------------------------------------------------------
__global__ __launch_bounds__(256) void qterm_kernel(
    const int* __restrict__ s, const int* __restrict__ r,
    const float* __restrict__ ent, const float* __restrict__ rel,
    const float* __restrict__ W, const float* __restrict__ b, int B)
{
    const int QB = 16;
    __shared__ float s_sh[QB][H];
    __shared__ float r_sh[QB][H];
    __shared__ int sidx[QB], ridx[QB];

    int q0  = blockIdx.x * QB;
    int tid = threadIdx.x;

    if (tid < QB) {
        int q = q0 + tid;
        sidx[tid] = (q < B) ? s[q] : 0;
        ridx[tid] = (q < B) ? r[q] : 0;
    }
    __syncthreads();

    for (int idx = tid; idx < QB * H; idx += 256) {
        int qq = idx >> 8, k = idx & (H - 1);
        s_sh[qq][k] = ent[(size_t)sidx[qq] * H + k];
        r_sh[qq][k] = rel[(size_t)ridx[qq] * H + k];
    }
    __syncthreads();

    int j = tid;
    float bj = b[j];
    float acc[QB];
#pragma unroll
    for (int qq = 0; qq < QB; qq++) acc[qq] = bj;

    for (int k = 0; k < H; k++) {
        float w2 = W[(size_t)(H + k) * H + j];
        float w3 = W[(size_t)(2 * H + k) * H + j];
#pragma unroll
        for (int qq = 0; qq < QB; qq++)
            acc[qq] = fmaf(s_sh[qq][k], w2, fmaf(r_sh[qq][k], w3, acc[qq]));
    }

#pragma unroll
    for (int qq = 0; qq < QB; qq++) {
        int q = q0 + qq;
        if (q < B) g_qterm[(size_t)q * H + j] = acc[qq];
    }
}

// ---------------------------------------------------------------------------
// Kernel 2b: segment offsets from sorted seg_ids.
// ---------------------------------------------------------------------------
__global__ __launch_bounds__(256) void boundary_kernel(
    const int* __restrict__ seg_ids, int N, int num_seg)
{
    int i = blockIdx.x * blockDim.x + threadIdx.x;
    if (i >= N) return;
    int sc = seg_ids[i];
    int sp = (i == 0) ? -1 : seg_ids[i - 1];
    for (int t = sp + 1; t <= sc; t++) g_off[t] = i;
    if (i == N - 1) {
        for (int t = sc + 1; t <= num_seg; t++) g_off[t] = N;
    }
}

// ---------------------------------------------------------------------------
// Kernel 3 (FUSED score + softmax + aggregation + output assembly).
// One warp per segment. qterm row & v_s live in registers for the whole
// segment (loaded once, not per neighbor). Online softmax: running max m,
// denom d, rescaled accumulator acc[8] — single pass over neighbors, each
// neighbor costing exactly two 1KB row gathers (entW1 + ent).
// out row: [agg(256) | ss(256) | rr(256)], zero row if segment empty.
// ---------------------------------------------------------------------------
__global__ __launch_bounds__(256) void fused_kernel(
    const int* __restrict__ s, const int* __restrict__ r,
    const int* __restrict__ nbr_ids,
    const float* __restrict__ ent, const float* __restrict__ rel,
    const float* __restrict__ v_s,
    float* __restrict__ out, int num_seg)
{
    int seg  = (int)((blockIdx.x * (unsigned)blockDim.x + threadIdx.x) >> 5);
    int lane = threadIdx.x & 31;
    if (seg >= num_seg) return;

    float* orow = out + (size_t)seg * (3 * H);
    float4* w4  = reinterpret_cast<float4*>(orow) + lane * 2;

    int lo = g_off[seg];
    int hi = g_off[seg + 1];

    if (lo >= hi) {
        float4 z = make_float4(0.f, 0.f, 0.f, 0.f);
#pragma unroll
        for (int c = 0; c < 3; c++) {
            w4[c * 64 + 0] = z;
            w4[c * 64 + 1] = z;
        }
        return;
    }

    int q = seg / SEQ_LEN;

    // Per-segment constants in registers: qterm row + v_s (8 floats/lane each)
    const float4* qtp = reinterpret_cast<const float4*>(g_qterm + (size_t)q * H) + lane * 2;
    const float4* vvp = reinterpret_cast<const float4*>(v_s) + lane * 2;
    float4 qt0 = qtp[0], qt1 = qtp[1];
    float4 vv0 = vvp[0], vv1 = vvp[1];

    float m = -INFINITY;        // running max (identical across lanes)
    float d = 0.f;              // running denom (identical across lanes)
    float4 acc0 = make_float4(0.f, 0.f, 0.f, 0.f);
    float4 acc1 = make_float4(0.f, 0.f, 0.f, 0.f);

    for (int i = lo; i < hi; i++) {
        int nid = nbr_ids[i];   // warp-uniform broadcast load

        // ---- score: sum_j v[j]*tanh(entW1[nid,j] + qterm[q,j]) ----
        const float4* ep = reinterpret_cast<const float4*>(g_entW1 + (size_t)nid * H) + lane * 2;
        float4 e0 = ep[0], e1 = ep[1];

        float t = tanh_approx(e0.x + qt0.x) * vv0.x;
        t = fmaf(tanh_approx(e0.y + qt0.y), vv0.y, t);
        t = fmaf(tanh_approx(e0.z + qt0.z), vv0.z, t);
        t = fmaf(tanh_approx(e0.w + qt0.w), vv0.w, t);
        t = fmaf(tanh_approx(e1.x + qt1.x), vv1.x, t);
        t = fmaf(tanh_approx(e1.y + qt1.y), vv1.y, t);
        t = fmaf(tanh_approx(e1.z + qt1.z), vv1.z, t);
        t = fmaf(tanh_approx(e1.w + qt1.w), vv1.w, t);
#pragma unroll
        for (int off = 16; off > 0; off >>= 1)
            t += __shfl_xor_sync(0xFFFFFFFFu, t, off);
        // t now identical across lanes

        // ---- online softmax update ----
        if (t > m) {
            float sc = __expf(m - t);   // first iter: exp(-inf)=0 -> resets cleanly
            d *= sc;
            acc0.x *= sc; acc0.y *= sc; acc0.z *= sc; acc0.w *= sc;
            acc1.x *= sc; acc1.y *= sc; acc1.z *= sc; acc1.w *= sc;
            m = t;
        }
        float p = __expf(t - m);
        d += p;

        // ---- weighted accumulate of raw embedding row ----
        const float4* emp = reinterpret_cast<const float4*>(ent + (size_t)nid * H) + lane * 2;
        float4 g0 = emp[0], g1 = emp[1];
        acc0.x = fmaf(p, g0.x, acc0.x); acc0.y = fmaf(p, g0.y, acc0.y);
        acc0.z = fmaf(p, g0.z, acc0.z); acc0.w = fmaf(p, g0.w, acc0.w);
        acc1.x = fmaf(p, g1.x, acc1.x); acc1.y = fmaf(p, g1.y, acc1.y);
        acc1.z = fmaf(p, g1.z, acc1.z); acc1.w = fmaf(p, g1.w, acc1.w);
    }

    float inv = 1.f / d;
    acc0.x *= inv; acc0.y *= inv; acc0.z *= inv; acc0.w *= inv;
    acc1.x *= inv; acc1.y *= inv; acc1.z *= inv; acc1.w *= inv;

    int sid = s[q];
    int rid = r[q];

    w4[0] = acc0;
    w4[1] = acc1;

    const float4* se = reinterpret_cast<const float4*>(ent + (size_t)sid * H) + lane * 2;
    w4[64 + 0] = se[0];
    w4[64 + 1] = se[1];

    const float4* re = reinterpret_cast<const float4*>(rel + (size_t)rid * H) + lane * 2;
    w4[128 + 0] = re[0];
    w4[128 + 1] = re[1];
}

// ---------------------------------------------------------------------------
extern "C" void kernel_launch(void* const* d_in, const int* in_sizes, int n_in,
                              void* d_out, int out_size)
{
    const int*   s    = (const int*)d_in[0];
    const int*   r    = (const int*)d_in[1];
    const int*   nbr  = (const int*)d_in[2];
    const int*   seg  = (const int*)d_in[3];
    const float* ent  = (const float*)d_in[4];
    const float* rel  = (const float*)d_in[5];
    const float* W    = (const float*)d_in[6];
    const float* b    = (const float*)d_in[7];
    const float* vs   = (const float*)d_in[8];
    float*       out  = (float*)d_out;

    int B  = in_sizes[0];
    int N  = in_sizes[2];
    int NE = in_sizes[4] / H;
    int num_seg = B * SEQ_LEN;

    // K1: entW1 = ent_embeds @ W1
    dim3 g1(2, (NE + 127) / 128);
    sgemm_entW1<<<g1, 256>>>(ent, W, NE);

    // K2: qterm = s_emb@W2 + r_emb@W3 + b
    qterm_kernel<<<(B + 15) / 16, 256>>>(s, r, ent, rel, W, b, B);

    // K2b: segment offsets (sorted seg_ids)
    boundary_kernel<<<(N + 255) / 256, 256>>>(seg, N, num_seg);

    // K3: fused score + online softmax + aggregation (1 warp / segment)
    int blocks3 = (num_seg + 7) / 8;
    fused_kernel<<<blocks3, 256>>>(s, r, nbr, ent, rel, vs, out, num_seg);
}

// round 10
// speedup vs baseline: 1.2331x; 1.0064x over previous
#include <cuda_runtime.h>
#include <cuda_bf16.h>
#include <math.h>

// Problem constants (match reference shapes)
#define H        256
#define SEQ_LEN  10
#define MAX_ENT  20000
#define MAX_B    2048
#define MAX_N    327680
#define MAX_SEG  (MAX_B * SEQ_LEN)

// Scratch (device globals — no allocation allowed)
__device__ float g_entW1[(size_t)MAX_ENT * H];   // ent_embeds @ W1
__device__ float g_qterm[(size_t)MAX_B * H];     // s@W2 + r@W3 + b
__device__ int   g_off[MAX_SEG + 1];             // segment offsets

__device__ __forceinline__ float tanh_approx(float x)
{
    float y;
    asm("tanh.approx.f32 %0, %1;" : "=f"(y) : "f"(x));
    return y;
}

// ---------------------------------------------------------------------------
// Kernel 1: entW1[M,256] = ent_embeds[M,256] @ W_attn[0:256, 0:256]
// 128x128 tile, 8x8 microtile, BK=8, 256 threads, register prefetch.
// Plain scalar FFMA mainloop (FFMA2/f32x2 experiment reverted — regression).
// ---------------------------------------------------------------------------
__global__ __launch_bounds__(256) void sgemm_entW1(
    const float* __restrict__ A, const float* __restrict__ W, int M)
{
    const int BM = 128, BK = 8;
    __shared__ float As[BK][BM];
    __shared__ float Bs[BK][BM];

    int tid  = threadIdx.x;
    int row0 = blockIdx.y * BM;
    int col0 = blockIdx.x * BM;

    int ar = tid >> 1;            // 0..127
    int ac = (tid & 1) * 4;       // 0 or 4
    int bk = tid >> 5;            // 0..7
    int bj = (tid & 31) * 4;      // 0..124
    int tx = tid & 15;
    int ty = tid >> 4;

    float acc[8][8];
#pragma unroll
    for (int i = 0; i < 8; i++)
#pragma unroll
        for (int j = 0; j < 8; j++) acc[i][j] = 0.f;

    // prologue: stage k0 = 0
    float4 av = make_float4(0.f, 0.f, 0.f, 0.f);
    if (row0 + ar < M)
        av = *reinterpret_cast<const float4*>(A + (size_t)(row0 + ar) * H + ac);
    float4 bv = *reinterpret_cast<const float4*>(W + (size_t)bk * H + col0 + bj);

    for (int k0 = 0; k0 < H; k0 += BK) {
        As[ac + 0][ar] = av.x;
        As[ac + 1][ar] = av.y;
        As[ac + 2][ar] = av.z;
        As[ac + 3][ar] = av.w;
        *reinterpret_cast<float4*>(&Bs[bk][bj]) = bv;
        __syncthreads();

        // prefetch next tile while computing this one
        if (k0 + BK < H) {
            if (row0 + ar < M)
                av = *reinterpret_cast<const float4*>(A + (size_t)(row0 + ar) * H + k0 + BK + ac);
            bv = *reinterpret_cast<const float4*>(W + (size_t)(k0 + BK + bk) * H + col0 + bj);
        }

#pragma unroll
        for (int kk = 0; kk < BK; kk++) {
            float a[8], b[8];
            *reinterpret_cast<float4*>(a)     = *reinterpret_cast<float4*>(&As[kk][ty * 4]);
            *reinterpret_cast<float4*>(a + 4) = *reinterpret_cast<float4*>(&As[kk][64 + ty * 4]);
            *reinterpret_cast<float4*>(b)     = *reinterpret_cast<float4*>(&Bs[kk][tx * 4]);
            *reinterpret_cast<float4*>(b + 4) = *reinterpret_cast<float4*>(&Bs[kk][64 + tx * 4]);
#pragma unroll
            for (int i = 0; i < 8; i++)
#pragma unroll
                for (int j = 0; j < 8; j++)
                    acc[i][j] = fmaf(a[i], b[j], acc[i][j]);
        }
        __syncthreads();
    }

#pragma unroll
    for (int i = 0; i < 8; i++) {
        int rr = row0 + ((i < 4) ? (ty * 4 + i) : (64 + ty * 4 + (i - 4)));
        if (rr >= M) continue;
        float4 v0 = make_float4(acc[i][0], acc[i][1], acc[i][2], acc[i][3]);
        float4 v1 = make_float4(acc[i][4], acc[i][5], acc[i][6], acc[i][7]);
        *reinterpret_cast<float4*>(g_entW1 + (size_t)rr * H + col0 + tx * 4)      = v0;
        *reinterpret_cast<float4*>(g_entW1 + (size_t)rr * H + col0 + 64 + tx * 4) = v1;
    }
}

// ---------------------------------------------------------------------------
// Kernel 2: qterm[q, j] = b[j] + sum_k s_emb[q,k]*W2[k,j] + r_emb[q,k]*W3[k,j]
// ---------------------------------------------------------------------------
__global__ __launch_bounds__(256) void qterm_kernel(
    const int* __restrict__ s, const int* __restrict__ r,
    const float* __restrict__ ent, const float* __restrict__ rel,
    const float* __restrict__ W, const float* __restrict__ b, int B)
{
    const int QB = 16;
    __shared__ float s_sh[QB][H];
    __shared__ float r_sh[QB][H];
    __shared__ int sidx[QB], ridx[QB];

    int q0  = blockIdx.x * QB;
    int tid = threadIdx.x;

    if (tid < QB) {
        int q = q0 + tid;
        sidx[tid] = (q < B) ? s[q] : 0;
        ridx[tid] = (q < B) ? r[q] : 0;
    }
    __syncthreads();

    for (int idx = tid; idx < QB * H; idx += 256) {
        int qq = idx >> 8, k = idx & (H - 1);
        s_sh[qq][k] = ent[(size_t)sidx[qq] * H + k];
        r_sh[qq][k] = rel[(size_t)ridx[qq] * H + k];
    }
    __syncthreads();

    int j = tid;
    float bj = b[j];
    float acc[QB];
#pragma unroll
    for (int qq = 0; qq < QB; qq++) acc[qq] = bj;

    for (int k = 0; k < H; k++) {
        float w2 = W[(size_t)(H + k) * H + j];
        float w3 = W[(size_t)(2 * H + k) * H + j];
#pragma unroll
        for (int qq = 0; qq < QB; qq++)
            acc[qq] = fmaf(s_sh[qq][k], w2, fmaf(r_sh[qq][k], w3, acc[qq]));
    }

#pragma unroll
    for (int qq = 0; qq < QB; qq++) {
        int q = q0 + qq;
        if (q < B) g_qterm[(size_t)q * H + j] = acc[qq];
    }
}

// ---------------------------------------------------------------------------
// Kernel 2b: segment offsets from sorted seg_ids.
// ---------------------------------------------------------------------------
__global__ __launch_bounds__(256) void boundary_kernel(
    const int* __restrict__ seg_ids, int N, int num_seg)
{
    int i = blockIdx.x * blockDim.x + threadIdx.x;
    if (i >= N) return;
    int sc = seg_ids[i];
    int sp = (i == 0) ? -1 : seg_ids[i - 1];
    for (int t = sp + 1; t <= sc; t++) g_off[t] = i;
    if (i == N - 1) {
        for (int t = sc + 1; t <= num_seg; t++) g_off[t] = N;
    }
}

// ---------------------------------------------------------------------------
// Kernel 3 (FUSED, unroll-by-2): score + online softmax + aggregation.
// One warp per segment. Two neighbors processed per iteration:
//  - both entW1 rows AND both ent rows are loaded up front (the ent gather
//    does not depend on the score, so it hides behind the shuffle chains)
//  - the two 5-step shfl reductions interleave, overlapping their latency
//  - one max/rescale per pair instead of per neighbor.
// ---------------------------------------------------------------------------
__global__ __launch_bounds__(256) void fused_kernel(
    const int* __restrict__ s, const int* __restrict__ r,
    const int* __restrict__ nbr_ids,
    const float* __restrict__ ent, const float* __restrict__ rel,
    const float* __restrict__ v_s,
    float* __restrict__ out, int num_seg)
{
    int seg  = (int)((blockIdx.x * (unsigned)blockDim.x + threadIdx.x) >> 5);
    int lane = threadIdx.x & 31;
    if (seg >= num_seg) return;

    float* orow = out + (size_t)seg * (3 * H);
    float4* w4  = reinterpret_cast<float4*>(orow) + lane * 2;

    int lo = g_off[seg];
    int hi = g_off[seg + 1];

    if (lo >= hi) {
        float4 z = make_float4(0.f, 0.f, 0.f, 0.f);
#pragma unroll
        for (int c = 0; c < 3; c++) {
            w4[c * 64 + 0] = z;
            w4[c * 64 + 1] = z;
        }
        return;
    }

    int q = seg / SEQ_LEN;

    // Per-segment constants in registers
    const float4* qtp = reinterpret_cast<const float4*>(g_qterm + (size_t)q * H) + lane * 2;
    const float4* vvp = reinterpret_cast<const float4*>(v_s) + lane * 2;
    float4 qt0 = qtp[0], qt1 = qtp[1];
    float4 vv0 = vvp[0], vv1 = vvp[1];

    float m = -INFINITY;
    float d = 0.f;
    float4 acc0 = make_float4(0.f, 0.f, 0.f, 0.f);
    float4 acc1 = make_float4(0.f, 0.f, 0.f, 0.f);

    int i = lo;
    for (; i + 2 <= hi; i += 2) {
        int nidA = nbr_ids[i];
        int nidB = nbr_ids[i + 1];

        // issue all four row gathers up front (independent)
        const float4* eA = reinterpret_cast<const float4*>(g_entW1 + (size_t)nidA * H) + lane * 2;
        const float4* eB = reinterpret_cast<const float4*>(g_entW1 + (size_t)nidB * H) + lane * 2;
        const float4* gA = reinterpret_cast<const float4*>(ent + (size_t)nidA * H) + lane * 2;
        const float4* gB = reinterpret_cast<const float4*>(ent + (size_t)nidB * H) + lane * 2;
        float4 ea0 = eA[0], ea1 = eA[1];
        float4 eb0 = eB[0], eb1 = eB[1];
        float4 ga0 = gA[0], ga1 = gA[1];
        float4 gb0 = gB[0], gb1 = gB[1];

        // two independent score chains
        float tA = tanh_approx(ea0.x + qt0.x) * vv0.x;
        float tB = tanh_approx(eb0.x + qt0.x) * vv0.x;
        tA = fmaf(tanh_approx(ea0.y + qt0.y), vv0.y, tA);
        tB = fmaf(tanh_approx(eb0.y + qt0.y), vv0.y, tB);
        tA = fmaf(tanh_approx(ea0.z + qt0.z), vv0.z, tA);
        tB = fmaf(tanh_approx(eb0.z + qt0.z), vv0.z, tB);
        tA = fmaf(tanh_approx(ea0.w + qt0.w), vv0.w, tA);
        tB = fmaf(tanh_approx(eb0.w + qt0.w), vv0.w, tB);
        tA = fmaf(tanh_approx(ea1.x + qt1.x), vv1.x, tA);
        tB = fmaf(tanh_approx(eb1.x + qt1.x), vv1.x, tB);
        tA = fmaf(tanh_approx(ea1.y + qt1.y), vv1.y, tA);
        tB = fmaf(tanh_approx(eb1.y + qt1.y), vv1.y, tB);
        tA = fmaf(tanh_approx(ea1.z + qt1.z), vv1.z, tA);
        tB = fmaf(tanh_approx(eb1.z + qt1.z), vv1.z, tB);
        tA = fmaf(tanh_approx(ea1.w + qt1.w), vv1.w, tA);
        tB = fmaf(tanh_approx(eb1.w + qt1.w), vv1.w, tB);

        // interleaved butterfly reductions (latency overlapped)
#pragma unroll
        for (int off = 16; off > 0; off >>= 1) {
            tA += __shfl_xor_sync(0xFFFFFFFFu, tA, off);
            tB += __shfl_xor_sync(0xFFFFFFFFu, tB, off);
        }

        // online softmax: one rescale per pair
        float mnew = fmaxf(m, fmaxf(tA, tB));
        float sc = __expf(m - mnew);   // first pair: exp(-inf)=0 resets cleanly
        d *= sc;
        acc0.x *= sc; acc0.y *= sc; acc0.z *= sc; acc0.w *= sc;
        acc1.x *= sc; acc1.y *= sc; acc1.z *= sc; acc1.w *= sc;
        m = mnew;

        float pA = __expf(tA - m);
        float pB = __expf(tB - m);
        d += pA + pB;

        acc0.x = fmaf(pA, ga0.x, fmaf(pB, gb0.x, acc0.x));
        acc0.y = fmaf(pA, ga0.y, fmaf(pB, gb0.y, acc0.y));
        acc0.z = fmaf(pA, ga0.z, fmaf(pB, gb0.z, acc0.z));
        acc0.w = fmaf(pA, ga0.w, fmaf(pB, gb0.w, acc0.w));
        acc1.x = fmaf(pA, ga1.x, fmaf(pB, gb1.x, acc1.x));
        acc1.y = fmaf(pA, ga1.y, fmaf(pB, gb1.y, acc1.y));
        acc1.z = fmaf(pA, ga1.z, fmaf(pB, gb1.z, acc1.z));
        acc1.w = fmaf(pA, ga1.w, fmaf(pB, gb1.w, acc1.w));
    }

    // remainder (at most one neighbor)
    if (i < hi) {
        int nid = nbr_ids[i];
        const float4* ep = reinterpret_cast<const float4*>(g_entW1 + (size_t)nid * H) + lane * 2;
        const float4* gp = reinterpret_cast<const float4*>(ent + (size_t)nid * H) + lane * 2;
        float4 e0 = ep[0], e1 = ep[1];
        float4 g0 = gp[0], g1 = gp[1];

        float t = tanh_approx(e0.x + qt0.x) * vv0.x;
        t = fmaf(tanh_approx(e0.y + qt0.y), vv0.y, t);
        t = fmaf(tanh_approx(e0.z + qt0.z), vv0.z, t);
        t = fmaf(tanh_approx(e0.w + qt0.w), vv0.w, t);
        t = fmaf(tanh_approx(e1.x + qt1.x), vv1.x, t);
        t = fmaf(tanh_approx(e1.y + qt1.y), vv1.y, t);
        t = fmaf(tanh_approx(e1.z + qt1.z), vv1.z, t);
        t = fmaf(tanh_approx(e1.w + qt1.w), vv1.w, t);
#pragma unroll
        for (int off = 16; off > 0; off >>= 1)
            t += __shfl_xor_sync(0xFFFFFFFFu, t, off);

        float mnew = fmaxf(m, t);
        float sc = __expf(m - mnew);
        d *= sc;
        acc0.x *= sc; acc0.y *= sc; acc0.z *= sc; acc0.w *= sc;
        acc1.x *= sc; acc1.y *= sc; acc1.z *= sc; acc1.w *= sc;
        m = mnew;

        float p = __expf(t - m);
        d += p;
        acc0.x = fmaf(p, g0.x, acc0.x); acc0.y = fmaf(p, g0.y, acc0.y);
        acc0.z = fmaf(p, g0.z, acc0.z); acc0.w = fmaf(p, g0.w, acc0.w);
        acc1.x = fmaf(p, g1.x, acc1.x); acc1.y = fmaf(p, g1.y, acc1.y);
        acc1.z = fmaf(p, g1.z, acc1.z); acc1.w = fmaf(p, g1.w, acc1.w);
    }

    float inv = 1.f / d;
    acc0.x *= inv; acc0.y *= inv; acc0.z *= inv; acc0.w *= inv;
    acc1.x *= inv; acc1.y *= inv; acc1.z *= inv; acc1.w *= inv;

    int sid = s[q];
    int rid = r[q];

    w4[0] = acc0;
    w4[1] = acc1;

    const float4* se = reinterpret_cast<const float4*>(ent + (size_t)sid * H) + lane * 2;
    w4[64 + 0] = se[0];
    w4[64 + 1] = se[1];

    const float4* re = reinterpret_cast<const float4*>(rel + (size_t)rid * H) + lane * 2;
    w4[128 + 0] = re[0];
    w4[128 + 1] = re[1];
}

// ---------------------------------------------------------------------------
extern "C" void kernel_launch(void* const* d_in, const int* in_sizes, int n_in,
                              void* d_out, int out_size)
{
    const int*   s    = (const int*)d_in[0];
    const int*   r    = (const int*)d_in[1];
    const int*   nbr  = (const int*)d_in[2];
    const int*   seg  = (const int*)d_in[3];
    const float* ent  = (const float*)d_in[4];
    const float* rel  = (const float*)d_in[5];
    const float* W    = (const float*)d_in[6];
    const float* b    = (const float*)d_in[7];
    const float* vs   = (const float*)d_in[8];
    float*       out  = (float*)d_out;

    int B  = in_sizes[0];
    int N  = in_sizes[2];
    int NE = in_sizes[4] / H;
    int num_seg = B * SEQ_LEN;

    // K1: entW1 = ent_embeds @ W1
    dim3 g1(2, (NE + 127) / 128);
    sgemm_entW1<<<g1, 256>>>(ent, W, NE);

    // K2: qterm = s_emb@W2 + r_emb@W3 + b
    qterm_kernel<<<(B + 15) / 16, 256>>>(s, r, ent, rel, W, b, B);

    // K2b: segment offsets (sorted seg_ids)
    boundary_kernel<<<(N + 255) / 256, 256>>>(seg, N, num_seg);

    // K3: fused score + online softmax + aggregation (1 warp / segment)
    int blocks3 = (num_seg + 7) / 8;
    fused_kernel<<<blocks3, 256>>>(s, r, nbr, ent, rel, vs, out, num_seg);
}